// round 14
// baseline (speedup 1.0000x reference)
#include <cuda_runtime.h>

typedef unsigned long long u64t;

__device__ __forceinline__ u64t fma2(u64t a, u64t b, u64t c) {
    u64t d;
    asm("fma.rn.f32x2 %0, %1, %2, %3;" : "=l"(d) : "l"(a), "l"(b), "l"(c));
    return d;
}
__device__ __forceinline__ u64t add2(u64t a, u64t b) {
    u64t d;
    asm("add.rn.f32x2 %0, %1, %2;" : "=l"(d) : "l"(a), "l"(b));
    return d;
}
__device__ __forceinline__ u64t pk2(float lo, float hi) {
    u64t d;
    asm("mov.b64 %0, {%1, %2};" : "=l"(d) : "f"(lo), "f"(hi));
    return d;
}
__device__ __forceinline__ void unpk(u64t v, float& lo, float& hi) {
    asm("mov.b64 {%0, %1}, %2;" : "=f"(lo), "=f"(hi) : "l"(v));
}
__device__ __forceinline__ float fsqrt_ap(float x) {
    float y;
    asm("sqrt.approx.f32 %0, %1;" : "=f"(y) : "f"(x));
    return y;
}
__device__ __forceinline__ u64t shx1(u64t v) {
    unsigned lo = (unsigned)v, hi = (unsigned)(v >> 32);
    lo = __shfl_xor_sync(0xffffffffu, lo, 1);
    hi = __shfl_xor_sync(0xffffffffu, hi, 1);
    return ((u64t)hi << 32) | lo;
}

#define MAXB 131072
// element-major scratch: 288 floats/element = 24 joints x [rot9 | jtr3] (16B-aligned blocks)
__device__ float g_scr[(size_t)MAXB * 288];

// ---- weight region (u64t units), R10 packed layout (sW0 in f'-order) ----
// x-order (new k): [rot 0..8, jtr 9..11, feat 12..17, bone 18, pad 19]
//   old-k map K(m): m<12 -> m ; 12..17 -> m+1 ; 18 -> 12 ; 19 -> zero
// sW1': [24 j][10 kp][20 r]  u64 = (W1[j][r][K(2kp)], W1[j][r][K(2kp+1)])
// sW2 : [24 j][20 k][3 dp]   (k=19 row = b2; fed by hs[9]==1 on odd lane)
// sW0': [144 kp][6 d]        u64 = (W0[d][F(2kp)], W0[d][F(2kp+1)])   F = f'->f
// sB1': [24 j][20 r]         u64 = (b1, 0)
// sB0': [6 d]                u64 = (b0, 0)
#define OW1 0
#define OW2 4800
#define OW0 6240
#define OB1 7104
#define OB0 7584
#define SM_U64 7590            // 60720 B (weights only)
#define SMEM_BYTES (SM_U64 * 8)

// ---- repack: [B,24,9]+[B,24,3] -> scratch [B][24][12], both sides coalesced ----
__global__ void __launch_bounds__(256)
repack_kernel(const float* __restrict__ rots, const float* __restrict__ jtrs, int n)
{
    int idx = blockIdx.x * 256 + threadIdx.x;       // output float4 index
    if (idx >= n * 72) return;
    int e = idx / 72, q = idx - e * 72;
    int f0 = 4 * q;
    float v[4];
#pragma unroll
    for (int c = 0; c < 4; ++c) {
        int f = f0 + c;
        int J = f / 12, i = f - 12 * J;
        v[c] = (i < 9) ? rots[(size_t)e * 216 + 9 * J + i]
                       : jtrs[(size_t)e * 72 + 3 * J + (i - 9)];
    }
    ((float4*)g_scr)[idx] = make_float4(v[0], v[1], v[2], v[3]);
}

template<int J, int PS, int WS>
__device__ __forceinline__ void do_joint(
    const float* __restrict__ sc, float* __restrict__ oe,
    int half, const u64t* __restrict__ sm,
    u64t (&fslot)[4][3], float (&jx)[4], float (&jy)[4], float (&jz)[4],
    const u64t (&g)[3])
{
    // 12 inputs of joint J: 3 x LDG.128 from the aligned block (independent of chain)
    u64t xp[10];
    ulonglong2 q2;
    {
        const ulonglong2* xq = (const ulonglong2*)(sc + 12 * J);
        ulonglong2 q0 = xq[0], q1 = xq[1]; q2 = xq[2];
        xp[0] = q0.x; xp[1] = q0.y; xp[2] = q1.x; xp[3] = q1.y;
        xp[4] = q2.x; xp[5] = q2.y;
    }
    float t8, j0, j1, j2;
    unpk(q2.x, t8, j0);                 // (rot8, jtr0)
    unpk(q2.y, j1, j2);                 // (jtr1, jtr2)
    (void)t8;

    float dx, dy, dz;
    if (PS < 0) { dx = j0; dy = j1; dz = j2; }
    else {
        const int P = (PS < 0) ? 0 : PS;
        dx = j0 - jx[P]; dy = j1 - jy[P]; dz = j2 - jz[P];
    }
    float bone = fsqrt_ap(dx*dx + dy*dy + dz*dz);
    jx[WS] = j0; jy[WS] = j1; jz[WS] = j2;

    if (PS < 0) { xp[6] = g[0]; xp[7] = g[1]; xp[8] = g[2]; }
    else {
        const int P = (PS < 0) ? 0 : PS;
        xp[6] = fslot[P][0]; xp[7] = fslot[P][1]; xp[8] = fslot[P][2];
    }
    xp[9] = pk2(bone, bone);            // hi weight is 0

    // ---- layer 1: 10 rows (this half), acc = (even-kp, odd-kp) partials ----
    u64t acc[10];
    {
        const ulonglong2* bb = (const ulonglong2*)(sm + OB1 + J*20 + 10*half);
        ulonglong2 c0 = bb[0], c1 = bb[1], c2 = bb[2], c3 = bb[3], c4 = bb[4];
        acc[0]=c0.x; acc[1]=c0.y; acc[2]=c1.x; acc[3]=c1.y; acc[4]=c2.x;
        acc[5]=c2.y; acc[6]=c3.x; acc[7]=c3.y; acc[8]=c4.x; acc[9]=c4.y;
    }
    const u64t* wb = sm + OW1 + (J*10)*20 + 10*half;
#pragma unroll
    for (int i = 0; i < 10; ++i) {
        const ulonglong2* wr = (const ulonglong2*)(wb + i*20);
        ulonglong2 wa = wr[0], wc = wr[1], wd = wr[2], we = wr[3], wf = wr[4];
        u64t xx = xp[i];
        acc[0] = fma2(xx, wa.x, acc[0]);
        acc[1] = fma2(xx, wa.y, acc[1]);
        acc[2] = fma2(xx, wc.x, acc[2]);
        acc[3] = fma2(xx, wc.y, acc[3]);
        acc[4] = fma2(xx, wd.x, acc[4]);
        acc[5] = fma2(xx, wd.y, acc[5]);
        acc[6] = fma2(xx, we.x, acc[6]);
        acc[7] = fma2(xx, we.y, acc[7]);
        acc[8] = fma2(xx, wf.x, acc[8]);
        acc[9] = fma2(xx, wf.y, acc[9]);
    }

    // combine even/odd-kp partials + relu
    float hs[10];
#pragma unroll
    for (int r = 0; r < 10; ++r) {
        float a, b; unpk(acc[r], a, b);
        hs[r] = fmaxf(a + b, 0.f);
    }
    if (half) hs[9] = 1.0f;             // global row 19 -> feeds b2 row (k=19)

    // ---- layer 2: preload 30 contiguous u64 weights, FMA burst ----
    ulonglong2 wz[15];
    {
        const ulonglong2* wp = (const ulonglong2*)(sm + OW2 + (J*20 + 10*half)*3);
#pragma unroll
        for (int i = 0; i < 15; ++i) wz[i] = wp[i];
    }
    u64t o0 = 0ull, o1 = 0ull, o2 = 0ull;
#pragma unroll
    for (int i = 0; i < 5; ++i) {
        u64t x0 = pk2(hs[2*i],   hs[2*i]);
        u64t x1 = pk2(hs[2*i+1], hs[2*i+1]);
        o0 = fma2(x0, wz[3*i  ].x, o0);
        o1 = fma2(x0, wz[3*i  ].y, o1);
        o2 = fma2(x0, wz[3*i+1].x, o2);
        o0 = fma2(x1, wz[3*i+1].y, o0);
        o1 = fma2(x1, wz[3*i+2].x, o1);
        o2 = fma2(x1, wz[3*i+2].y, o2);
    }
    o0 = add2(o0, shx1(o0));
    o1 = add2(o1, shx1(o1));
    o2 = add2(o2, shx1(o2));

    fslot[WS][0] = o0; fslot[WS][1] = o1; fslot[WS][2] = o2;

    // direct global store: 8B-aligned (e*576 + 24J bytes)
    u64t* d = (u64t*)(oe + 6*J);
    if (half == 0) { d[0] = o0; d[1] = o1; }
    else           { d[2] = o2; }
}

__global__ void __launch_bounds__(512, 1)
pose_kernel(const float* __restrict__ W0, const float* __restrict__ b0,
            const float* __restrict__ W1, const float* __restrict__ b1,
            const float* __restrict__ W2, const float* __restrict__ b2,
            float* __restrict__ out)
{
    extern __shared__ u64t sm[];
    const int tid = threadIdx.x;

    // ---- weight packing (R10 layout; sW0 permuted to f'-order) ----
    for (int idx = tid; idx < 24*10*20; idx += 512) {   // sW1' [j][kp][20 r]
        int r = idx % 20; int t = idx / 20; int i = t % 10; int j = t / 10;
        int m0 = 2*i, m1 = 2*i + 1;
        float lo = 0.f, hi = 0.f;
        if (r < 19) {
            int k0 = (m0 < 12) ? m0 : (m0 < 18 ? m0 + 1 : 12);
            lo = W1[(j*19 + r)*19 + k0];
            if (m1 < 19) {
                int k1 = (m1 < 12) ? m1 : (m1 < 18 ? m1 + 1 : 12);
                hi = W1[(j*19 + r)*19 + k1];
            }
        }
        sm[OW1 + idx] = pk2(lo, hi);
    }
    for (int idx = tid; idx < 24*20*3; idx += 512) {    // sW2 [j][20 k][3 dp]
        int dp = idx % 3; int t = idx / 3; int k = t % 20; int j = t / 20;
        float lo, hi;
        if (k < 19) { lo = W2[(j*6 + 2*dp)*19 + k]; hi = W2[(j*6 + 2*dp + 1)*19 + k]; }
        else        { lo = b2[j*6 + 2*dp];          hi = b2[j*6 + 2*dp + 1]; }
        sm[OW2 + idx] = pk2(lo, hi);
    }
    for (int idx = tid; idx < 144*6; idx += 512) {      // sW0' [144 kp][6 d], f'-order
        int d = idx % 6; int kp = idx / 6;
        int m0 = 2*kp, m1 = 2*kp + 1;
        int J0 = m0/12, i0 = m0%12;
        int f0 = (i0 < 9) ? (9*J0 + i0) : (216 + 3*J0 + (i0 - 9));
        int J1 = m1/12, i1 = m1%12;
        int f1 = (i1 < 9) ? (9*J1 + i1) : (216 + 3*J1 + (i1 - 9));
        sm[OW0 + idx] = pk2(W0[d*288 + f0], W0[d*288 + f1]);
    }
    for (int idx = tid; idx < 24*20; idx += 512) {      // sB1' [j][20 r]
        int r = idx % 20; int j = idx / 20;
        float lo = (r < 19) ? b1[j*19 + r] : 0.f;
        sm[OB1 + idx] = pk2(lo, 0.f);
    }
    if (tid < 6) sm[OB0 + tid] = pk2(b0[tid], 0.f);
    __syncthreads();

    const int p    = tid >> 1;          // element within CTA block
    const int half = tid & 1;           // row/k half
    size_t e = (size_t)blockIdx.x * 256 + p;

    const float* sc = g_scr + e * 288;
    float*       oe = out   + e * 144;

    // ---- pass 1: gfeat partial over this lane's 144 f'-features (contiguous) ----
    u64t a6[6];
    if (half == 0) {
#pragma unroll
        for (int d = 0; d < 6; ++d) a6[d] = sm[OB0 + d];
    } else {
#pragma unroll
        for (int d = 0; d < 6; ++d) a6[d] = 0ull;
    }
    {
        const ulonglong2* xq = (const ulonglong2*)(sc + 144*half);   // 36 x 16B
        const u64t* wbase = sm + OW0 + (72*half)*6;
#pragma unroll 4
        for (int q = 0; q < 36; ++q) {
            ulonglong2 xv = xq[q];                      // kp 2q, 2q+1
            const ulonglong2* wp = (const ulonglong2*)(wbase + q*12);
            ulonglong2 w0 = wp[0], w1 = wp[1], w2 = wp[2];
            ulonglong2 w3 = wp[3], w4 = wp[4], w5 = wp[5];
            a6[0] = fma2(xv.x, w0.x, a6[0]);
            a6[1] = fma2(xv.x, w0.y, a6[1]);
            a6[2] = fma2(xv.x, w1.x, a6[2]);
            a6[3] = fma2(xv.x, w1.y, a6[3]);
            a6[4] = fma2(xv.x, w2.x, a6[4]);
            a6[5] = fma2(xv.x, w2.y, a6[5]);
            a6[0] = fma2(xv.y, w3.x, a6[0]);
            a6[1] = fma2(xv.y, w3.y, a6[1]);
            a6[2] = fma2(xv.y, w4.x, a6[2]);
            a6[3] = fma2(xv.y, w4.y, a6[3]);
            a6[4] = fma2(xv.y, w5.x, a6[4]);
            a6[5] = fma2(xv.y, w5.y, a6[5]);
        }
    }
    u64t g[3];
#pragma unroll
    for (int dp = 0; dp < 3; ++dp) {
        float a0, a1, c0, c1;
        unpk(a6[2*dp],     a0, a1);
        unpk(a6[2*dp + 1], c0, c1);
        u64t pr = pk2(a0 + a1, c0 + c1);
        g[dp] = add2(pr, shx1(pr));
    }

    // ---- pass 2: joint chain, 4-slot register liveness (proven mapping) ----
    u64t fslot[4][3];
    float jx[4], jy[4], jz[4];

    do_joint< 0,-1,0>(sc, oe, half, sm, fslot, jx, jy, jz, g);
    do_joint< 1, 0,1>(sc, oe, half, sm, fslot, jx, jy, jz, g);
    do_joint< 2, 0,2>(sc, oe, half, sm, fslot, jx, jy, jz, g);
    do_joint< 3, 0,3>(sc, oe, half, sm, fslot, jx, jy, jz, g);
    do_joint< 4, 1,0>(sc, oe, half, sm, fslot, jx, jy, jz, g);
    do_joint< 5, 2,1>(sc, oe, half, sm, fslot, jx, jy, jz, g);
    do_joint< 6, 3,2>(sc, oe, half, sm, fslot, jx, jy, jz, g);
    do_joint< 7, 0,3>(sc, oe, half, sm, fslot, jx, jy, jz, g);
    do_joint< 8, 1,0>(sc, oe, half, sm, fslot, jx, jy, jz, g);
    do_joint< 9, 2,1>(sc, oe, half, sm, fslot, jx, jy, jz, g);
    do_joint<10, 3,2>(sc, oe, half, sm, fslot, jx, jy, jz, g);
    do_joint<11, 0,2>(sc, oe, half, sm, fslot, jx, jy, jz, g);
    do_joint<12, 1,2>(sc, oe, half, sm, fslot, jx, jy, jz, g);
    do_joint<13, 1,0>(sc, oe, half, sm, fslot, jx, jy, jz, g);
    do_joint<14, 1,3>(sc, oe, half, sm, fslot, jx, jy, jz, g);
    do_joint<15, 2,1>(sc, oe, half, sm, fslot, jx, jy, jz, g);
    do_joint<16, 0,1>(sc, oe, half, sm, fslot, jx, jy, jz, g);
    do_joint<17, 3,0>(sc, oe, half, sm, fslot, jx, jy, jz, g);
    do_joint<18, 1,3>(sc, oe, half, sm, fslot, jx, jy, jz, g);
    do_joint<19, 0,1>(sc, oe, half, sm, fslot, jx, jy, jz, g);
    do_joint<20, 3,0>(sc, oe, half, sm, fslot, jx, jy, jz, g);
    do_joint<21, 1,3>(sc, oe, half, sm, fslot, jx, jy, jz, g);
    do_joint<22, 0,1>(sc, oe, half, sm, fslot, jx, jy, jz, g);
    do_joint<23, 3,0>(sc, oe, half, sm, fslot, jx, jy, jz, g);
}

extern "C" void kernel_launch(void* const* d_in, const int* in_sizes, int n_in,
                              void* d_out, int out_size) {
    (void)n_in; (void)out_size;
    const float* rots = (const float*)d_in[0];
    const float* jtrs = (const float*)d_in[1];
    const float* W0   = (const float*)d_in[2];
    const float* b0   = (const float*)d_in[3];
    const float* W1   = (const float*)d_in[4];
    const float* b1   = (const float*)d_in[5];
    const float* W2   = (const float*)d_in[6];
    const float* b2   = (const float*)d_in[7];
    float* out = (float*)d_out;

    int n = in_sizes[0] / 216;        // B (131072)
    if (n > MAXB) n = MAXB;

    int rgrid = (n * 72 + 255) / 256;
    repack_kernel<<<rgrid, 256>>>(rots, jtrs, n);

    int grid = n / 256;
    cudaFuncSetAttribute(pose_kernel, cudaFuncAttributeMaxDynamicSharedMemorySize, SMEM_BYTES);
    pose_kernel<<<grid, 512, SMEM_BYTES>>>(W0, b0, W1, b1, W2, b2, out);
}